// round 16
// baseline (speedup 1.0000x reference)
#include <cuda_runtime.h>
#include <cuda_bf16.h>
#include <math.h>
#include <stdint.h>

// Problem constants
#define HH   50
#define WWD  50
#define CC   512
#define KKT  2048
#define NCLS 20
#define NPOS 2500
#define NOBJ 22500
#define DIN  4608
#define F6   9216
#define F7   4096

// Eigen gebp k-panel (bit-exactness of obj path depends on this)
#define EIG_KC 320
#define KC_TILES (EIG_KC / 16)

// ------------------------- scratch (device globals) --------------------------
__device__ __align__(16) float g_acol [NPOS * 2048];
__device__ __align__(16) float g_x    [NPOS * CC];
__device__ __align__(16) float g_wcomb[CC * 45];
__device__ __align__(16) float g_bcomb[48];
__device__ __align__(16) float g_obj  [NOBJ];
__device__ __align__(16) float g_regall[NOBJ * 4];
__device__            int   g_cnt  [NOBJ];
__device__            int   g_topk [KKT];
__device__ __align__(16) float g_h7   [(size_t)KKT * F7];
__device__ __align__(16) float g_h6f  [(size_t)KKT * F6];
__device__ __align__(16) float g_w8   [F7 * 40];
__device__ __align__(16) float g_b8   [40];
__device__ __align__(16) float g_logits[KKT * 40];
__device__ __align__(16) float g_dsm  [KKT * NCLS];
// int8 digit operands + scales (scales stored as row/col max)
__device__ __align__(16) char  g_pq1 [(size_t)KKT * DIN];
__device__ __align__(16) char  g_pq2 [(size_t)KKT * DIN];
__device__ __align__(16) char  g_h6q1[(size_t)KKT * F6];
__device__ __align__(16) char  g_h6q2[(size_t)KKT * F6];
__device__ __align__(16) char  g_w6q1[(size_t)F6 * DIN];   // [N][K]
__device__ __align__(16) char  g_w6q2[(size_t)F6 * DIN];
__device__ __align__(16) char  g_w7q1[(size_t)F7 * F6];
__device__ __align__(16) char  g_w7q2[(size_t)F7 * F6];
__device__ __align__(16) float g_amax [KKT];
__device__ __align__(16) float g_h6max[KKT];
__device__ __align__(16) float g_w6max[F6];
__device__ __align__(16) float g_w7max[F7];

__device__ __forceinline__ float4 f4zero() { return make_float4(0.f, 0.f, 0.f, 0.f); }

__device__ __forceinline__ uint32_t smem_u32(const void* p) {
    uint32_t a;
    asm("{ .reg .u64 t; cvta.to.shared.u64 t, %1; cvt.u32.u64 %0, t; }" : "=r"(a) : "l"(p));
    return a;
}
__device__ __forceinline__ void ldsm_x4(uint32_t a, uint32_t* r) {
    asm volatile("ldmatrix.sync.aligned.m8n8.x4.shared.b16 {%0,%1,%2,%3}, [%4];"
        : "=r"(r[0]), "=r"(r[1]), "=r"(r[2]), "=r"(r[3]) : "r"(a));
}
__device__ __forceinline__ void mma_s8(int* d, const uint32_t* a, const uint32_t* b) {
    asm volatile("mma.sync.aligned.m16n8k32.row.col.s32.s8.s8.s32 "
        "{%0,%1,%2,%3},{%4,%5,%6,%7},{%8,%9},{%0,%1,%2,%3};"
        : "+r"(d[0]), "+r"(d[1]), "+r"(d[2]), "+r"(d[3])
        : "r"(a[0]), "r"(a[1]), "r"(a[2]), "r"(a[3]), "r"(b[0]), "r"(b[1]));
}
#define CP_ASYNC16(dst, src) \
    asm volatile("cp.async.cg.shared.global [%0], [%1], 16;" :: "r"(dst), "l"(src) : "memory")
#define CP_COMMIT() asm volatile("cp.async.commit_group;" ::: "memory")
#define CP_WAIT1()  asm volatile("cp.async.wait_group 1;" ::: "memory")

// two-digit int8 quantization: x ~= s*(q1 + q2/254), s = m/127
__device__ __forceinline__ void quant2(float x, float inv, char* o1, char* o2) {
    float qf = x * inv;
    int a = __float2int_rn(qf);
    a = max(-127, min(127, a));
    int b = __float2int_rn((qf - (float)a) * 254.f);
    b = max(-127, min(127, b));
    *o1 = (char)a; *o2 = (char)b;
}

// XLA f32 tanh rational approx, non-contracted
__device__ __forceinline__ float xla_tanh_f32(float x) {
    float ax = fabsf(x);
    if (ax < 0.0004f) return x;
    float xc = fminf(7.90531110763549805f, fmaxf(-7.90531110763549805f, x));
    float x2 = __fmul_rn(xc, xc);
    float p = -2.76076847742355e-16f;
    p = __fadd_rn(__fmul_rn(p, x2), 2.00018790482477e-13f);
    p = __fadd_rn(__fmul_rn(p, x2), -8.60467152213735e-11f);
    p = __fadd_rn(__fmul_rn(p, x2), 5.12229709037114e-08f);
    p = __fadd_rn(__fmul_rn(p, x2), 1.48572235717979e-05f);
    p = __fadd_rn(__fmul_rn(p, x2), 6.37261928875436e-04f);
    p = __fadd_rn(__fmul_rn(p, x2), 4.89352455891786e-03f);
    p = __fmul_rn(p, xc);
    float q = 1.19825839466702e-06f;
    q = __fadd_rn(__fmul_rn(q, x2), 1.18534705686654e-04f);
    q = __fadd_rn(__fmul_rn(q, x2), 2.26843463243900e-03f);
    q = __fadd_rn(__fmul_rn(q, x2), 4.89352518554385e-03f);
    return __fdiv_rn(p, q);
}
__device__ __forceinline__ float xla_logistic_f32(float x) {
    return __fadd_rn(0.5f, __fmul_rn(0.5f, xla_tanh_f32(__fmul_rn(0.5f, x))));
}

// ------------------------- aux weight packing --------------------------------
__global__ void build_aux_kernel(const float* __restrict__ cls_w, const float* __restrict__ cls_b,
                                 const float* __restrict__ reg_w, const float* __restrict__ reg_b,
                                 const float* __restrict__ c8w,   const float* __restrict__ c8b,
                                 const float* __restrict__ d8w,   const float* __restrict__ d8b)
{
    int idx = blockIdx.x * blockDim.x + threadIdx.x;
    const int N_WC = CC * 45;
    const int N_W8 = F7 * 40;
    if (idx < N_WC) {
        int ci = idx / 45, o = idx % 45;
        g_wcomb[idx] = (o < 9) ? cls_w[ci * 9 + o] : reg_w[ci * 36 + (o - 9)];
    } else if (idx < N_WC + N_W8) {
        int t = idx - N_WC;
        int k = t / 40, o = t % 40;
        g_w8[t] = (o < 20) ? c8w[k * 20 + o] : d8w[k * 20 + (o - 20)];
    } else if (idx < N_WC + N_W8 + 45) {
        int o = idx - N_WC - N_W8;
        g_bcomb[o] = (o < 9) ? cls_b[o] : reg_b[o - 9];
    } else if (idx < N_WC + N_W8 + 45 + 40) {
        int o = idx - N_WC - N_W8 - 45;
        g_b8[o] = (o < 20) ? c8b[o] : d8b[o - 20];
    }
}

// ------------- per-column |max| of W[K,N] via atomicMax-as-uint ---------------
__global__ void wmax_kernel(const float* __restrict__ W, float* __restrict__ wmax,
                            int K, int N)
{
    int n = blockIdx.x * 256 + threadIdx.x;
    int ks = (K / 16) * blockIdx.y;
    int ke = ks + K / 16;
    float m = 0.f;
    for (int k = ks; k < ke; k++)
        m = fmaxf(m, fabsf(W[(size_t)k * N + n]));
    atomicMax((unsigned*)&wmax[n], __float_as_uint(m));
}

// ---------- weight transpose + int8 digit quant: W[K,N] -> Q[N][K] -----------
__global__ void wquant_kernel(const float* __restrict__ W, const float* __restrict__ wmax,
                              char* __restrict__ Q1, char* __restrict__ Q2,
                              int K, int N)
{
    __shared__ float ts[32][33];
    int k0 = blockIdx.y * 32, n0 = blockIdx.x * 32;
    int tx = threadIdx.x, ty = threadIdx.y;
#pragma unroll
    for (int r = 0; r < 4; r++)
        ts[ty + r * 8][tx] = W[(size_t)(k0 + ty + r * 8) * N + n0 + tx];
    __syncthreads();
#pragma unroll
    for (int r = 0; r < 4; r++) {
        int n = n0 + ty + r * 8;
        float inv = 127.f / fmaxf(wmax[n], 1e-30f);
        float v = ts[tx][ty + r * 8];
        size_t o = (size_t)n * K + k0 + tx;
        quant2(v, inv, &Q1[o], &Q2[o]);
    }
}

// ------------------------- im2col for 2x2 SAME conv --------------------------
__global__ void im2col_kernel(const float* __restrict__ feat)
{
    int r = blockIdx.x;
    int p = r >> 2, tap = r & 3;
    int h = p / WWD, w = p % WWD;
    int dy = tap >> 1, dx = tap & 1;
    int hh = h + dy, ww = w + dx;
    float4* dst = (float4*)(g_acol + (size_t)p * 2048 + tap * 512);
    if (hh < HH && ww < WWD) {
        const float4* src = (const float4*)(feat + ((size_t)hh * WWD + ww) * CC);
        dst[threadIdx.x] = src[threadIdx.x];
    } else {
        dst[threadIdx.x] = f4zero();
    }
}

// --------------- RPN conv GEMM, Eigen-panelized fp32 (kc = 320) --------------
__global__ void __launch_bounds__(256) conv_sgemm_kernel(
    const float* __restrict__ A, const float* __restrict__ B,
    const float* __restrict__ bias, float* __restrict__ X)
{
    const int BM = 128, BN = 64, BK = 16;
    const int K = 2048, N = 512, M = NPOS;
    __shared__ __align__(16) float As[2][BK][BM];
    __shared__ __align__(16) float Bs[2][BK][BN];

    const int tid = threadIdx.x;
    const int tx = tid & 15, ty = tid >> 4;
    const int m0 = blockIdx.y * BM;
    const int n0 = blockIdx.x * BN;

    const int ar = tid >> 1;
    const int ak = (tid & 1) * 8;
    const int br = tid >> 4;
    const int bn = (tid & 15) << 2;

    const bool av = (m0 + ar) < M;
    const float* Ap = A + (size_t)(m0 + ar) * K + ak;
    const float* Bp = B + (size_t)br * N + n0 + bn;

    float accT[8][4], accP[8][4];
#pragma unroll
    for (int i = 0; i < 8; i++)
#pragma unroll
        for (int j = 0; j < 4; j++) { accT[i][j] = 0.f; accP[i][j] = 0.f; }

    float4 pa0, pa1, pb;
    pa0 = av ? *(const float4*)(Ap)     : f4zero();
    pa1 = av ? *(const float4*)(Ap + 4) : f4zero();
    pb  = *(const float4*)(Bp);
    {
        As[0][ak + 0][ar] = pa0.x; As[0][ak + 1][ar] = pa0.y;
        As[0][ak + 2][ar] = pa0.z; As[0][ak + 3][ar] = pa0.w;
        As[0][ak + 4][ar] = pa1.x; As[0][ak + 5][ar] = pa1.y;
        As[0][ak + 6][ar] = pa1.z; As[0][ak + 7][ar] = pa1.w;
        *(float4*)&Bs[0][br][bn] = pb;
    }
    __syncthreads();

    const int nt = K / BK;
    for (int t = 0; t < nt; ++t) {
        const int buf = t & 1;
        if (t > 0 && (t % KC_TILES) == 0) {
#pragma unroll
            for (int i = 0; i < 8; i++)
#pragma unroll
                for (int j = 0; j < 4; j++) {
                    accT[i][j] = __fadd_rn(accT[i][j], accP[i][j]);
                    accP[i][j] = 0.f;
                }
        }
        if (t + 1 < nt) {
            int k0 = (t + 1) * BK;
            pa0 = av ? *(const float4*)(Ap + k0)     : f4zero();
            pa1 = av ? *(const float4*)(Ap + k0 + 4) : f4zero();
            pb  = *(const float4*)(Bp + (size_t)k0 * N);
        }
#pragma unroll
        for (int kk = 0; kk < BK; ++kk) {
            float da[8], db[4];
#pragma unroll
            for (int i = 0; i < 8; i++) da[i] = As[buf][kk][ty * 8 + i];
#pragma unroll
            for (int j = 0; j < 4; j++) db[j] = Bs[buf][kk][tx * 4 + j];
#pragma unroll
            for (int i = 0; i < 8; i++)
#pragma unroll
                for (int j = 0; j < 4; j++)
                    accP[i][j] = fmaf(da[i], db[j], accP[i][j]);
        }
        if (t + 1 < nt) {
            int ob = buf ^ 1;
            As[ob][ak + 0][ar] = pa0.x; As[ob][ak + 1][ar] = pa0.y;
            As[ob][ak + 2][ar] = pa0.z; As[ob][ak + 3][ar] = pa0.w;
            As[ob][ak + 4][ar] = pa1.x; As[ob][ak + 5][ar] = pa1.y;
            As[ob][ak + 6][ar] = pa1.z; As[ob][ak + 7][ar] = pa1.w;
            *(float4*)&Bs[ob][br][bn] = pb;
            __syncthreads();
        }
    }

#pragma unroll
    for (int i = 0; i < 8; i++) {
        int r = m0 + ty * 8 + i;
        if (r < M) {
#pragma unroll
            for (int j = 0; j < 4; j++) {
                int c = n0 + tx * 4 + j;
                float dot = __fadd_rn(accT[i][j], accP[i][j]);
                float v = __fadd_rn(dot, bias[c]);
                X[(size_t)r * N + c] = fmaxf(v, 0.f);
            }
        }
    }
}

// ---- cls/reg heads: Eigen-panelized fp32 (panels [0,320) and [320,512)) -----
__global__ void __launch_bounds__(256) cls_reg_kernel()
{
    __shared__ __align__(16) float xs[8 * 512];
    int p0 = blockIdx.x * 8;
    int tid = threadIdx.x;
    for (int u = tid; u < 8 * 512; u += 256) {
        int pl = u >> 9;
        int p = p0 + pl;
        xs[u] = (p < NPOS) ? g_x[(size_t)p * CC + (u & 511)] : 0.f;
    }
    __syncthreads();
    for (int t = tid; t < 8 * 45; t += 256) {
        int pl = t / 45, o = t % 45;
        int p = p0 + pl;
        if (p >= NPOS) continue;
        const float* xrow = xs + pl * 512;
        float a0 = 0.f, a1 = 0.f;
#pragma unroll 8
        for (int ci = 0; ci < EIG_KC; ci++)
            a0 = fmaf(xrow[ci], g_wcomb[ci * 45 + o], a0);
#pragma unroll 8
        for (int ci = EIG_KC; ci < 512; ci++)
            a1 = fmaf(xrow[ci], g_wcomb[ci * 45 + o], a1);
        float dot = __fadd_rn(a0, a1);
        float lg = __fadd_rn(dot, g_bcomb[o]);
        if (o < 9) {
            g_obj[p * 9 + o] = xla_logistic_f32(lg);
        } else {
            g_regall[p * 36 + (o - 9)] = lg;
        }
    }
}

// ------------------ exact stable top-K (rank counting, 4x tiled) -------------
__global__ void __launch_bounds__(256) topk_count_kernel()
{
    __shared__ float sv[3750];
    int base = blockIdx.y * 3750;
    for (int jj = threadIdx.x; jj < 3750; jj += 256) sv[jj] = g_obj[base + jj];
    __syncthreads();
    int i0 = blockIdx.x * 1024 + threadIdx.x;
    float vi[4]; int cnt[4];
#pragma unroll
    for (int u = 0; u < 4; u++) {
        int i = i0 + u * 256;
        vi[u] = (i < NOBJ) ? g_obj[i] : -1.f;
        cnt[u] = 0;
    }
#pragma unroll 2
    for (int j = 0; j < 3750; j++) {
        float vj = sv[j];
        int gj = base + j;
#pragma unroll
        for (int u = 0; u < 4; u++) {
            int i = i0 + u * 256;
            cnt[u] += (vj > vi[u]) || (vj == vi[u] && gj < i);
        }
    }
#pragma unroll
    for (int u = 0; u < 4; u++) {
        int i = i0 + u * 256;
        if (i < NOBJ && cnt[u] > 0) atomicAdd(&g_cnt[i], cnt[u]);
    }
}

__global__ void topk_place_kernel()
{
    int i = blockIdx.x * 256 + threadIdx.x;
    if (i < NOBJ) {
        int c = g_cnt[i];
        if (c < KKT) g_topk[c] = i;
    }
}

// ---- ROI align (fused box decode) -> int8 digits + row max + out_boxes ------
__global__ void __launch_bounds__(256) roi_align_kernel(const float* __restrict__ feat,
                                                        float* __restrict__ out_boxes)
{
    __shared__ float pool[DIN];
    __shared__ float red[256];
    __shared__ float bx[4];
    __shared__ float sfx[3], sfy[3];
    __shared__ int sx0[3], sx1[3], sy0[3], sy1[3];
    int r = blockIdx.x;
    int tid = threadIdx.x;
    if (tid == 0) {
        int i = g_topk[r];
        float s0 = xla_logistic_f32(g_regall[i * 4 + 0]);
        float s1 = xla_logistic_f32(g_regall[i * 4 + 1]);
        float s2 = xla_logistic_f32(g_regall[i * 4 + 2]);
        float s3 = xla_logistic_f32(g_regall[i * 4 + 3]);
        float x1 = __fmul_rn(s0, 48.f);
        float x2 = __fadd_rn(__fadd_rn(x1, 1.f), __fmul_rn(s1, __fadd_rn(49.f, -x1)));
        float y1 = __fmul_rn(s2, 48.f);
        float y2 = __fadd_rn(__fadd_rn(y1, 1.f), __fmul_rn(s3, __fadd_rn(49.f, -y1)));
        bx[0] = x1; bx[1] = x2; bx[2] = y1; bx[3] = y2;
        out_boxes[r * 4 + 0] = x1; out_boxes[r * 4 + 1] = x2;
        out_boxes[r * 4 + 2] = y1; out_boxes[r * 4 + 3] = y2;
    }
    __syncthreads();
    if (tid < 3) {
        float x1 = bx[0], x2 = bx[1], y1 = bx[2], y2 = bx[3];
        float t = ((float)tid + 0.5f) / 3.0f;
        float xsv = x1 + (x2 - x1) * t;
        float ysv = y1 + (y2 - y1) * t;
        float x0f = floorf(xsv), y0f = floorf(ysv);
        sfx[tid] = xsv - x0f;  sfy[tid] = ysv - y0f;
        int x0 = min(max((int)x0f, 0), WWD - 1);
        int y0 = min(max((int)y0f, 0), HH - 1);
        sx0[tid] = x0; sx1[tid] = min(x0 + 1, WWD - 1);
        sy0[tid] = y0; sy1[tid] = min(y0 + 1, HH - 1);
    }
    __syncthreads();
    const float4* f4 = (const float4*)feat;
    for (int id = tid; id < 9 * 128; id += 256) {
        int cell = id >> 7, c4 = id & 127;
        int py = cell / 3, px = cell % 3;
        float fx = sfx[px], fy = sfy[py];
        float w00 = (1.f - fy) * (1.f - fx);
        float w01 = (1.f - fy) * fx;
        float w10 = fy * (1.f - fx);
        float w11 = fy * fx;
        float4 v00 = f4[(size_t)(sy0[py] * WWD + sx0[px]) * 128 + c4];
        float4 v01 = f4[(size_t)(sy0[py] * WWD + sx1[px]) * 128 + c4];
        float4 v10 = f4[(size_t)(sy1[py] * WWD + sx0[px]) * 128 + c4];
        float4 v11 = f4[(size_t)(sy1[py] * WWD + sx1[px]) * 128 + c4];
        float4 o;
        o.x = w00 * v00.x + w01 * v01.x + w10 * v10.x + w11 * v11.x;
        o.y = w00 * v00.y + w01 * v01.y + w10 * v10.y + w11 * v11.y;
        o.z = w00 * v00.z + w01 * v01.z + w10 * v10.z + w11 * v11.z;
        o.w = w00 * v00.w + w01 * v01.w + w10 * v10.w + w11 * v11.w;
        *(float4*)&pool[id * 4] = o;
    }
    __syncthreads();
    // row max
    float m = 0.f;
    for (int i = tid; i < DIN; i += 256) m = fmaxf(m, fabsf(pool[i]));
    red[tid] = m; __syncthreads();
    for (int s = 128; s > 0; s >>= 1) {
        if (tid < s) red[tid] = fmaxf(red[tid], red[tid + s]);
        __syncthreads();
    }
    m = red[0];
    if (tid == 0) g_amax[r] = m;
    float inv = 127.f / fmaxf(m, 1e-30f);
    for (int i = tid; i < DIN; i += 256) {
        size_t o = (size_t)r * DIN + i;
        quant2(pool[i], inv, &g_pq1[o], &g_pq2[o]);
    }
}

// ---------- per-row quantization of fp32 h6 -> int8 digits + row max ---------
__global__ void __launch_bounds__(256) rowquant_kernel()
{
    __shared__ float red[256];
    int r = blockIdx.x;
    int tid = threadIdx.x;
    const float* row = g_h6f + (size_t)r * F6;
    float m = 0.f;
    for (int i = tid; i < F6; i += 256) m = fmaxf(m, fabsf(row[i]));
    red[tid] = m; __syncthreads();
    for (int s = 128; s > 0; s >>= 1) {
        if (tid < s) red[tid] = fmaxf(red[tid], red[tid + s]);
        __syncthreads();
    }
    m = red[0];
    if (tid == 0) g_h6max[r] = m;
    float inv = 127.f / fmaxf(m, 1e-30f);
    for (int i = tid; i < F6; i += 256) {
        size_t o = (size_t)r * F6 + i;
        quant2(row[i], inv, &g_h6q1[o], &g_h6q2[o]);
    }
}

// ===== int8 two-digit GEMM on mma.sync s8 (2x bf16 rate): C = relu(...) =====
// x ~= sa*(q1+q2/254), y ~= sb*(p1+p2/254); out = ma*mb*(S1/127^2 + S23/(127^2*254))
// 512 threads / 16 warps, CTA tile 128x128, warp tile 32x32, K-chunk 64 int8,
// 3-stage cp.async pipeline, pitch 80B. 3 passes: q1p1->S1, q1p2+q2p1->S23.
#define MMARRB 10240                  // 128 rows * 80B
#define MMBUFB (4 * MMARRB)           // 40960 per stage (4 arrays)
#define MMSMEM (3 * MMBUFB)           // 122880
__global__ void __launch_bounds__(512, 1) mma_gemm_s8_kernel(
    const char* __restrict__ Aq1, const char* __restrict__ Aq2,
    const char* __restrict__ Bq1, const char* __restrict__ Bq2,
    const float* __restrict__ amax, const float* __restrict__ bmax,
    const float* __restrict__ bias, float* __restrict__ Cf,
    int M, int N, int K)
{
    extern __shared__ __align__(16) char smem_bf[];
    const uint32_t sbase = smem_u32(smem_bf);
    const int tid = threadIdx.x;
    const int wid = tid >> 5, lane = tid & 31;
    const int m0 = blockIdx.y * 128, n0 = blockIdx.x * 128;
    const int wm = wid >> 2, wn = wid & 3;

    const char* gsrc[4] = {
        Aq1 + (size_t)m0 * K, Aq2 + (size_t)m0 * K,
        Bq1 + (size_t)n0 * K, Bq2 + (size_t)n0 * K };

    const int grow = tid >> 2;                 // 0..127
    const int gcol = (tid & 3) * 16;           // byte col within 64B row
    const uint32_t sst = (uint32_t)grow * 80 + (uint32_t)gcol;

    // ldmatrix (b16 units = int8 pairs) lane addressing
    const int aRow = (lane & 7) + ((lane >> 3) & 1) * 8;
    const uint32_t aColB = (uint32_t)(lane >> 4) * 16;     // quadrant byte offset
    const int bqRow = ((lane >> 4) << 3) + (lane & 7);
    const uint32_t bqColB = ((lane >> 3) & 1) * 16;

    int s1a[2][4][4], s23[2][4][4];
#pragma unroll
    for (int mt = 0; mt < 2; mt++)
#pragma unroll
        for (int nt = 0; nt < 4; nt++)
#pragma unroll
            for (int r = 0; r < 4; r++) { s1a[mt][nt][r] = 0; s23[mt][nt][r] = 0; }

    const int NC = K / 64;
#pragma unroll
    for (int pc = 0; pc < 2; pc++) {
        int k0 = pc * 64;
#pragma unroll
        for (int a = 0; a < 4; a++) {
            uint32_t dst = sbase + (uint32_t)pc * MMBUFB + (uint32_t)a * MMARRB + sst;
            const char* src = gsrc[a] + (size_t)grow * K + k0 + gcol;
            CP_ASYNC16(dst, src);
        }
        CP_COMMIT();
    }

    for (int t = 0; t < NC; ++t) {
        CP_WAIT1();
        __syncthreads();
        const uint32_t bb = sbase + (uint32_t)(t % 3) * MMBUFB;
#pragma unroll
        for (int kk = 0; kk < 2; kk++) {           // two k32 halves of 64B row
            const uint32_t akb = (uint32_t)kk * 32 + aColB;
            const uint32_t bkb = (uint32_t)kk * 32 + bqColB;
            uint32_t af[2][4], bf[8];
            // A q1
#pragma unroll
            for (int mt = 0; mt < 2; mt++)
                ldsm_x4(bb + (uint32_t)(wm * 32 + mt * 16 + aRow) * 80 + akb, af[mt]);
            // B q2 -> S23 += q1*p2
#pragma unroll
            for (int p = 0; p < 2; p++)
                ldsm_x4(bb + 3 * MMARRB + (uint32_t)(wn * 32 + p * 16 + bqRow) * 80 + bkb, &bf[p * 4]);
#pragma unroll
            for (int mt = 0; mt < 2; mt++)
#pragma unroll
                for (int nt = 0; nt < 4; nt++)
                    mma_s8(s23[mt][nt], af[mt], &bf[nt * 2]);
            // B q1 -> S1 += q1*p1
#pragma unroll
            for (int p = 0; p < 2; p++)
                ldsm_x4(bb + 2 * MMARRB + (uint32_t)(wn * 32 + p * 16 + bqRow) * 80 + bkb, &bf[p * 4]);
#pragma unroll
            for (int mt = 0; mt < 2; mt++)
#pragma unroll
                for (int nt = 0; nt < 4; nt++)
                    mma_s8(s1a[mt][nt], af[mt], &bf[nt * 2]);
            // A q2 -> S23 += q2*p1
#pragma unroll
            for (int mt = 0; mt < 2; mt++)
                ldsm_x4(bb + 1 * MMARRB + (uint32_t)(wm * 32 + mt * 16 + aRow) * 80 + akb, af[mt]);
#pragma unroll
            for (int mt = 0; mt < 2; mt++)
#pragma unroll
                for (int nt = 0; nt < 4; nt++)
                    mma_s8(s23[mt][nt], af[mt], &bf[nt * 2]);
        }
        if (t + 2 < NC) {
            int c = t + 2;
            int k0 = c * 64;
            uint32_t db = sbase + (uint32_t)(c % 3) * MMBUFB;
#pragma unroll
            for (int a = 0; a < 4; a++) {
                uint32_t dst = db + (uint32_t)a * MMARRB + sst;
                const char* src = gsrc[a] + (size_t)grow * K + k0 + gcol;
                CP_ASYNC16(dst, src);
            }
            CP_COMMIT();
        }
    }

    const float c1 = 1.f / (127.f * 127.f);
    const float c2 = c1 / 254.f;
#pragma unroll
    for (int mt = 0; mt < 2; mt++) {
#pragma unroll
        for (int nt = 0; nt < 4; nt++) {
#pragma unroll
            for (int rp = 0; rp < 2; rp++) {
                int row = m0 + wm * 32 + mt * 16 + (lane >> 2) + rp * 8;
                int col = n0 + wn * 32 + nt * 8 + 2 * (lane & 3);
                float sa = __ldg(&amax[row]);
                float sb0 = __ldg(&bmax[col]);
                float sb1 = __ldg(&bmax[col + 1]);
                float d0 = fmaf((float)s23[mt][nt][rp * 2 + 0], c2,
                                (float)s1a[mt][nt][rp * 2 + 0] * c1);
                float d1 = fmaf((float)s23[mt][nt][rp * 2 + 1], c2,
                                (float)s1a[mt][nt][rp * 2 + 1] * c1);
                float v0 = fmaxf(sa * sb0 * d0 + __ldg(&bias[col]), 0.f);
                float v1 = fmaxf(sa * sb1 * d1 + __ldg(&bias[col + 1]), 0.f);
                float2 fv; fv.x = v0; fv.y = v1;
                *(float2*)&Cf[(size_t)row * N + col] = fv;
            }
        }
    }
}

// ---------- FC8 (two 4096x20 heads, N=40) + fused class softmax (d) ----------
__global__ void __launch_bounds__(256) fc8_kernel()
{
    __shared__ float hs[32 * 65];
    __shared__ float ws[64 * 40];
    __shared__ float ls[32][41];
    int r0 = blockIdx.x * 32;
    int tid = threadIdx.x;
    int rl = tid >> 3, og = tid & 7;
    float acc[5] = {0.f, 0.f, 0.f, 0.f, 0.f};
    for (int k0 = 0; k0 < F7; k0 += 64) {
        __syncthreads();
        for (int u = tid; u < 32 * 16; u += 256) {
            int rr = u >> 4, k4 = u & 15;
            float4 v = *(const float4*)&g_h7[(size_t)(r0 + rr) * F7 + k0 + k4 * 4];
            hs[rr * 65 + k4 * 4 + 0] = v.x;
            hs[rr * 65 + k4 * 4 + 1] = v.y;
            hs[rr * 65 + k4 * 4 + 2] = v.z;
            hs[rr * 65 + k4 * 4 + 3] = v.w;
        }
        for (int u = tid; u < 64 * 40; u += 256)
            ws[u] = g_w8[(size_t)k0 * 40 + u];
        __syncthreads();
#pragma unroll 4
        for (int k = 0; k < 64; k++) {
            float h = hs[rl * 65 + k];
            const float* wp = &ws[k * 40 + og * 5];
#pragma unroll
            for (int j = 0; j < 5; j++) acc[j] = fmaf(h, wp[j], acc[j]);
        }
    }
#pragma unroll
    for (int j = 0; j < 5; j++) {
        int o = og * 5 + j;
        float lg = acc[j] + g_b8[o];
        g_logits[(size_t)(r0 + rl) * 40 + o] = lg;
        ls[rl][o] = lg;
    }
    __syncthreads();
    if (tid < 32) {
        const float* lp = &ls[tid][20];
        float m = -1e30f;
#pragma unroll
        for (int o = 0; o < 20; o++) m = fmaxf(m, lp[o]);
        float e[20]; float s = 0.f;
#pragma unroll
        for (int o = 0; o < 20; o++) { e[o] = expf(lp[o] - m); s += e[o]; }
        float* dp = &g_dsm[(size_t)(r0 + tid) * 20];
#pragma unroll
        for (int o = 0; o < 20; o++) dp[o] = e[o] / s;
    }
}

// --------- softmax over regions (c) + scores + clipped class sums ------------
__global__ void __launch_bounds__(256) final_kernel(float* __restrict__ out,
                                                    float* __restrict__ out_scores)
{
    __shared__ float red[256];
    __shared__ float mS[2];
    int j = blockIdx.x, tid = threadIdx.x;

    float m = -1e30f;
    for (int r = tid; r < KKT; r += 256) m = fmaxf(m, g_logits[(size_t)r * 40 + j]);
    red[tid] = m; __syncthreads();
    for (int s = 128; s > 0; s >>= 1) {
        if (tid < s) red[tid] = fmaxf(red[tid], red[tid + s]);
        __syncthreads();
    }
    if (tid == 0) mS[0] = red[0];
    __syncthreads();
    m = mS[0];

    float s = 0.f;
    for (int r = tid; r < KKT; r += 256) s += expf(g_logits[(size_t)r * 40 + j] - m);
    red[tid] = s; __syncthreads();
    for (int st = 128; st > 0; st >>= 1) {
        if (tid < st) red[tid] += red[tid + st];
        __syncthreads();
    }
    if (tid == 0) mS[1] = red[0];
    __syncthreads();
    float S = mS[1];

    float tot = 0.f;
    for (int r = tid; r < KKT; r += 256) {
        float cv = expf(g_logits[(size_t)r * 40 + j] - m) / S;
        float sc = cv * g_dsm[r * 20 + j];
        out_scores[r * 20 + j] = sc;
        tot += sc;
    }
    red[tid] = tot; __syncthreads();
    for (int st = 128; st > 0; st >>= 1) {
        if (tid < st) red[tid] += red[tid + st];
        __syncthreads();
    }
    if (tid == 0) out[j] = fminf(fmaxf(red[0], 0.f), 1.f);
}

// ------------------------- launcher ------------------------------------------
extern "C" void kernel_launch(void* const* d_in, const int* in_sizes, int n_in,
                              void* d_out, int out_size)
{
    const float* features = (const float*)d_in[0];
    const float* rpn_w  = (const float*)d_in[2];
    const float* rpn_b  = (const float*)d_in[3];
    const float* cls_w  = (const float*)d_in[4];
    const float* cls_b  = (const float*)d_in[5];
    const float* reg_w  = (const float*)d_in[6];
    const float* reg_b  = (const float*)d_in[7];
    const float* fc6_w  = (const float*)d_in[8];
    const float* fc6_b  = (const float*)d_in[9];
    const float* fc7_w  = (const float*)d_in[10];
    const float* fc7_b  = (const float*)d_in[11];
    const float* fc8c_w = (const float*)d_in[12];
    const float* fc8c_b = (const float*)d_in[13];
    const float* fc8d_w = (const float*)d_in[14];
    const float* fc8d_b = (const float*)d_in[15];

    float* out        = (float*)d_out;
    float* out_scores = out + NCLS;
    float* out_boxes  = out + NCLS + KKT * NCLS;

    void *p_acol, *p_x, *p_cnt;
    void *p_pq1, *p_pq2, *p_h6q1, *p_h6q2, *p_w6q1, *p_w6q2, *p_w7q1, *p_w7q2;
    void *p_amax, *p_h6max, *p_w6max, *p_w7max, *p_h6f, *p_h7;
    cudaGetSymbolAddress(&p_acol,  g_acol);
    cudaGetSymbolAddress(&p_x,     g_x);
    cudaGetSymbolAddress(&p_cnt,   g_cnt);
    cudaGetSymbolAddress(&p_pq1,   g_pq1);
    cudaGetSymbolAddress(&p_pq2,   g_pq2);
    cudaGetSymbolAddress(&p_h6q1,  g_h6q1);
    cudaGetSymbolAddress(&p_h6q2,  g_h6q2);
    cudaGetSymbolAddress(&p_w6q1,  g_w6q1);
    cudaGetSymbolAddress(&p_w6q2,  g_w6q2);
    cudaGetSymbolAddress(&p_w7q1,  g_w7q1);
    cudaGetSymbolAddress(&p_w7q2,  g_w7q2);
    cudaGetSymbolAddress(&p_amax,  g_amax);
    cudaGetSymbolAddress(&p_h6max, g_h6max);
    cudaGetSymbolAddress(&p_w6max, g_w6max);
    cudaGetSymbolAddress(&p_w7max, g_w7max);
    cudaGetSymbolAddress(&p_h6f,   g_h6f);
    cudaGetSymbolAddress(&p_h7,    g_h7);

    cudaFuncSetAttribute(mma_gemm_s8_kernel, cudaFuncAttributeMaxDynamicSharedMemorySize, MMSMEM);

    static cudaStream_t s_aux = nullptr;
    static cudaEvent_t ev_fork = nullptr, ev_join = nullptr;
    if (s_aux == nullptr) {
        cudaStreamCreateWithFlags(&s_aux, cudaStreamNonBlocking);
        cudaEventCreateWithFlags(&ev_fork, cudaEventDisableTiming);
        cudaEventCreateWithFlags(&ev_join, cudaEventDisableTiming);
    }

    // fork: weight-prep on s_aux, obj path on default stream
    cudaEventRecord(ev_fork, 0);
    cudaStreamWaitEvent(s_aux, ev_fork, 0);

    cudaMemsetAsync(p_w6max, 0, F6 * sizeof(float), s_aux);
    cudaMemsetAsync(p_w7max, 0, F7 * sizeof(float), s_aux);
    build_aux_kernel<<<(CC*45 + F7*40 + 85 + 255) / 256, 256, 0, s_aux>>>(
        cls_w, cls_b, reg_w, reg_b, fc8c_w, fc8c_b, fc8d_w, fc8d_b);
    wmax_kernel<<<dim3(F6 / 256, 16), 256, 0, s_aux>>>(fc6_w, (float*)p_w6max, DIN, F6);
    wmax_kernel<<<dim3(F7 / 256, 16), 256, 0, s_aux>>>(fc7_w, (float*)p_w7max, F6, F7);
    wquant_kernel<<<dim3(F6 / 32, DIN / 32), dim3(32, 8), 0, s_aux>>>(
        fc6_w, (const float*)p_w6max, (char*)p_w6q1, (char*)p_w6q2, DIN, F6);
    wquant_kernel<<<dim3(F7 / 32, F6 / 32), dim3(32, 8), 0, s_aux>>>(
        fc7_w, (const float*)p_w7max, (char*)p_w7q1, (char*)p_w7q2, F6, F7);
    cudaEventRecord(ev_join, s_aux);

    // obj path (bit-exact fp32, Eigen kc=320 panels)
    im2col_kernel<<<NPOS * 4, 128>>>(features);
    conv_sgemm_kernel<<<dim3(512 / 64, (NPOS + 127) / 128), 256>>>(
        (const float*)p_acol, rpn_w, rpn_b, (float*)p_x);
    cudaMemsetAsync(p_cnt, 0, NOBJ * sizeof(int), 0);

    cudaStreamWaitEvent(0, ev_join, 0);
    cls_reg_kernel<<<(NPOS + 7) / 8, 256>>>();

    topk_count_kernel<<<dim3(22, 6), 256>>>();
    topk_place_kernel<<<88, 256>>>();

    // ROI align + box decode + int8 quantization of pooled rows
    roi_align_kernel<<<KKT, 256>>>(features, out_boxes);

    // FC6 int8: [2048,4608] x [4608,9216]^T -> fp32 h6
    mma_gemm_s8_kernel<<<dim3(F6 / 128, KKT / 128), 512, MMSMEM>>>(
        (const char*)p_pq1, (const char*)p_pq2,
        (const char*)p_w6q1, (const char*)p_w6q2,
        (const float*)p_amax, (const float*)p_w6max,
        fc6_b, (float*)p_h6f, KKT, F6, DIN);

    // quantize h6 rows
    rowquant_kernel<<<KKT, 256>>>();

    // FC7 int8: [2048,9216] x [9216,4096]^T -> fp32 h7
    mma_gemm_s8_kernel<<<dim3(F7 / 128, KKT / 128), 512, MMSMEM>>>(
        (const char*)p_h6q1, (const char*)p_h6q2,
        (const char*)p_w7q1, (const char*)p_w7q2,
        (const float*)p_h6max, (const float*)p_w7max,
        fc7_b, (float*)p_h7, KKT, F7, F6);

    fc8_kernel<<<KKT / 32, 256>>>();
    final_kernel<<<NCLS, 256>>>(out, out_scores);

    (void)in_sizes; (void)n_in; (void)out_size;
}

// round 17
// speedup vs baseline: 2.2257x; 2.2257x over previous
#include <cuda_runtime.h>
#include <cuda_bf16.h>
#include <math.h>
#include <stdint.h>

// Problem constants
#define HH   50
#define WWD  50
#define CC   512
#define KKT  2048
#define NCLS 20
#define NPOS 2500
#define NOBJ 22500
#define DIN  4608
#define F6   9216
#define F7   4096

// Eigen gebp k-panel (bit-exactness of obj path depends on this)
#define EIG_KC 320
#define KC_TILES (EIG_KC / 16)

// ------------------------- scratch (device globals) --------------------------
__device__ __align__(16) float g_acol [NPOS * 2048];
__device__ __align__(16) float g_x    [NPOS * CC];
__device__ __align__(16) float g_wcomb[CC * 45];
__device__ __align__(16) float g_bcomb[48];
__device__ __align__(16) float g_obj  [NOBJ];
__device__ __align__(16) float g_regall[NOBJ * 4];
__device__            int   g_cnt  [NOBJ];
__device__            int   g_topk [KKT];
__device__ __align__(16) float g_h7   [(size_t)KKT * F7];
__device__ __align__(16) float g_w8   [F7 * 40];
__device__ __align__(16) float g_b8   [40];
__device__ __align__(16) float g_logits[KKT * 40];
__device__ __align__(16) float g_dsm  [KKT * NCLS];
// bf16 split operands
__device__ __align__(16) __nv_bfloat16 g_ph [(size_t)KKT * DIN];
__device__ __align__(16) __nv_bfloat16 g_pl [(size_t)KKT * DIN];
__device__ __align__(16) __nv_bfloat16 g_w6h[(size_t)F6 * DIN];   // [N][K]
__device__ __align__(16) __nv_bfloat16 g_w6l[(size_t)F6 * DIN];
__device__ __align__(16) __nv_bfloat16 g_w7h[(size_t)F7 * F6];
__device__ __align__(16) __nv_bfloat16 g_w7l[(size_t)F7 * F6];
__device__ __align__(16) __nv_bfloat16 g_h6h[(size_t)KKT * F6];
__device__ __align__(16) __nv_bfloat16 g_h6l[(size_t)KKT * F6];

__device__ __forceinline__ float4 f4zero() { return make_float4(0.f, 0.f, 0.f, 0.f); }

__device__ __forceinline__ uint32_t smem_u32(const void* p) {
    uint32_t a;
    asm("{ .reg .u64 t; cvta.to.shared.u64 t, %1; cvt.u32.u64 %0, t; }" : "=r"(a) : "l"(p));
    return a;
}
__device__ __forceinline__ void ldsm_x4(uint32_t a, uint32_t* r) {
    asm volatile("ldmatrix.sync.aligned.m8n8.x4.shared.b16 {%0,%1,%2,%3}, [%4];"
        : "=r"(r[0]), "=r"(r[1]), "=r"(r[2]), "=r"(r[3]) : "r"(a));
}
__device__ __forceinline__ void ldsm_x2(uint32_t a, uint32_t* r) {
    asm volatile("ldmatrix.sync.aligned.m8n8.x2.shared.b16 {%0,%1}, [%2];"
        : "=r"(r[0]), "=r"(r[1]) : "r"(a));
}
__device__ __forceinline__ void mma_bf16(float* d, const uint32_t* a, const uint32_t* b) {
    asm volatile("mma.sync.aligned.m16n8k16.row.col.f32.bf16.bf16.f32 "
        "{%0,%1,%2,%3},{%4,%5,%6,%7},{%8,%9},{%0,%1,%2,%3};"
        : "+f"(d[0]), "+f"(d[1]), "+f"(d[2]), "+f"(d[3])
        : "r"(a[0]), "r"(a[1]), "r"(a[2]), "r"(a[3]), "r"(b[0]), "r"(b[1]));
}
#define CP_ASYNC16(dst, src) \
    asm volatile("cp.async.cg.shared.global [%0], [%1], 16;" :: "r"(dst), "l"(src) : "memory")
#define CP_COMMIT() asm volatile("cp.async.commit_group;" ::: "memory")
#define CP_WAIT1()  asm volatile("cp.async.wait_group 1;" ::: "memory")

// XLA f32 tanh rational approx, non-contracted
__device__ __forceinline__ float xla_tanh_f32(float x) {
    float ax = fabsf(x);
    if (ax < 0.0004f) return x;
    float xc = fminf(7.90531110763549805f, fmaxf(-7.90531110763549805f, x));
    float x2 = __fmul_rn(xc, xc);
    float p = -2.76076847742355e-16f;
    p = __fadd_rn(__fmul_rn(p, x2), 2.00018790482477e-13f);
    p = __fadd_rn(__fmul_rn(p, x2), -8.60467152213735e-11f);
    p = __fadd_rn(__fmul_rn(p, x2), 5.12229709037114e-08f);
    p = __fadd_rn(__fmul_rn(p, x2), 1.48572235717979e-05f);
    p = __fadd_rn(__fmul_rn(p, x2), 6.37261928875436e-04f);
    p = __fadd_rn(__fmul_rn(p, x2), 4.89352455891786e-03f);
    p = __fmul_rn(p, xc);
    float q = 1.19825839466702e-06f;
    q = __fadd_rn(__fmul_rn(q, x2), 1.18534705686654e-04f);
    q = __fadd_rn(__fmul_rn(q, x2), 2.26843463243900e-03f);
    q = __fadd_rn(__fmul_rn(q, x2), 4.89352518554385e-03f);
    return __fdiv_rn(p, q);
}
__device__ __forceinline__ float xla_logistic_f32(float x) {
    return __fadd_rn(0.5f, __fmul_rn(0.5f, xla_tanh_f32(__fmul_rn(0.5f, x))));
}

// ------------------------- aux weight packing --------------------------------
__global__ void build_aux_kernel(const float* __restrict__ cls_w, const float* __restrict__ cls_b,
                                 const float* __restrict__ reg_w, const float* __restrict__ reg_b,
                                 const float* __restrict__ c8w,   const float* __restrict__ c8b,
                                 const float* __restrict__ d8w,   const float* __restrict__ d8b)
{
    int idx = blockIdx.x * blockDim.x + threadIdx.x;
    const int N_WC = CC * 45;
    const int N_W8 = F7 * 40;
    if (idx < N_WC) {
        int ci = idx / 45, o = idx % 45;
        g_wcomb[idx] = (o < 9) ? cls_w[ci * 9 + o] : reg_w[ci * 36 + (o - 9)];
    } else if (idx < N_WC + N_W8) {
        int t = idx - N_WC;
        int k = t / 40, o = t % 40;
        g_w8[t] = (o < 20) ? c8w[k * 20 + o] : d8w[k * 20 + (o - 20)];
    } else if (idx < N_WC + N_W8 + 45) {
        int o = idx - N_WC - N_W8;
        g_bcomb[o] = (o < 9) ? cls_b[o] : reg_b[o - 9];
    } else if (idx < N_WC + N_W8 + 45 + 40) {
        int o = idx - N_WC - N_W8 - 45;
        g_b8[o] = (o < 20) ? c8b[o] : d8b[o - 20];
    }
}

// ---------------- weight transpose + bf16 hi/lo split: W[K,N] -> T[N,K] ------
__global__ void wsplit_kernel(const float* __restrict__ W,
                              __nv_bfloat16* __restrict__ Th, __nv_bfloat16* __restrict__ Tl,
                              int K, int N)
{
    __shared__ float ts[32][33];
    int k0 = blockIdx.y * 32, n0 = blockIdx.x * 32;
    int tx = threadIdx.x, ty = threadIdx.y;
#pragma unroll
    for (int r = 0; r < 4; r++)
        ts[ty + r * 8][tx] = W[(size_t)(k0 + ty + r * 8) * N + n0 + tx];
    __syncthreads();
#pragma unroll
    for (int r = 0; r < 4; r++) {
        float v = ts[tx][ty + r * 8];
        __nv_bfloat16 hi = __float2bfloat16(v);
        float lo = v - __bfloat162float(hi);
        size_t o = (size_t)(n0 + ty + r * 8) * K + k0 + tx;
        Th[o] = hi;
        Tl[o] = __float2bfloat16(lo);
    }
}

// ------------------------- im2col for 2x2 SAME conv --------------------------
__global__ void im2col_kernel(const float* __restrict__ feat)
{
    int r = blockIdx.x;
    int p = r >> 2, tap = r & 3;
    int h = p / WWD, w = p % WWD;
    int dy = tap >> 1, dx = tap & 1;
    int hh = h + dy, ww = w + dx;
    float4* dst = (float4*)(g_acol + (size_t)p * 2048 + tap * 512);
    if (hh < HH && ww < WWD) {
        const float4* src = (const float4*)(feat + ((size_t)hh * WWD + ww) * CC);
        dst[threadIdx.x] = src[threadIdx.x];
    } else {
        dst[threadIdx.x] = f4zero();
    }
}

// --------------- RPN conv GEMM, Eigen-panelized fp32 (kc = 320) --------------
// Double-buffered SMEM, one barrier per K-tile. Per-output accumulation order
// (ascending k, fold every 320) unchanged -> obj path stays bit-exact.
__global__ void __launch_bounds__(256) conv_sgemm_kernel(
    const float* __restrict__ A, const float* __restrict__ B,
    const float* __restrict__ bias, float* __restrict__ X)
{
    const int BM = 64, BN = 64, BK = 16;
    const int K = 2048, N = 512, M = NPOS;
    __shared__ __align__(16) float As[2][BK][BM];
    __shared__ __align__(16) float Bs[2][BK][BN];

    const int tid = threadIdx.x;
    const int tx = tid & 15, ty = tid >> 4;
    const int m0 = blockIdx.y * BM;
    const int n0 = blockIdx.x * BN;

    const int ar = tid >> 2;
    const int ak = (tid & 3) << 2;
    const int br = tid >> 4;
    const int bn = (tid & 15) << 2;

    const bool av = (m0 + ar) < M;
    const float* Ap = A + (size_t)(m0 + ar) * K + ak;
    const float* Bp = B + (size_t)br * N + n0 + bn;

    float accT[4][4], accP[4][4];
#pragma unroll
    for (int i = 0; i < 4; i++)
#pragma unroll
        for (int j = 0; j < 4; j++) { accT[i][j] = 0.f; accP[i][j] = 0.f; }

    float4 pa, pb;
    pa = av ? *(const float4*)(Ap) : f4zero();
    pb = *(const float4*)(Bp);
    {
        As[0][ak + 0][ar] = pa.x; As[0][ak + 1][ar] = pa.y;
        As[0][ak + 2][ar] = pa.z; As[0][ak + 3][ar] = pa.w;
        *(float4*)&Bs[0][br][bn] = pb;
    }
    __syncthreads();

    const int nt = K / BK;
    for (int t = 0; t < nt; ++t) {
        const int buf = t & 1;
        if (t > 0 && (t % KC_TILES) == 0) {
#pragma unroll
            for (int i = 0; i < 4; i++)
#pragma unroll
                for (int j = 0; j < 4; j++) {
                    accT[i][j] = __fadd_rn(accT[i][j], accP[i][j]);
                    accP[i][j] = 0.f;
                }
        }
        if (t + 1 < nt) {
            int k0 = (t + 1) * BK;
            pa = av ? *(const float4*)(Ap + k0) : f4zero();
            pb = *(const float4*)(Bp + (size_t)k0 * N);
        }
#pragma unroll
        for (int kk = 0; kk < BK; ++kk) {
            float da[4], db[4];
#pragma unroll
            for (int i = 0; i < 4; i++) da[i] = As[buf][kk][ty * 4 + i];
#pragma unroll
            for (int j = 0; j < 4; j++) db[j] = Bs[buf][kk][tx * 4 + j];
#pragma unroll
            for (int i = 0; i < 4; i++)
#pragma unroll
                for (int j = 0; j < 4; j++)
                    accP[i][j] = fmaf(da[i], db[j], accP[i][j]);
        }
        if (t + 1 < nt) {
            int ob = buf ^ 1;
            As[ob][ak + 0][ar] = pa.x; As[ob][ak + 1][ar] = pa.y;
            As[ob][ak + 2][ar] = pa.z; As[ob][ak + 3][ar] = pa.w;
            *(float4*)&Bs[ob][br][bn] = pb;
            __syncthreads();
        }
    }

#pragma unroll
    for (int i = 0; i < 4; i++) {
        int r = m0 + ty * 4 + i;
        if (r < M) {
#pragma unroll
            for (int j = 0; j < 4; j++) {
                int c = n0 + tx * 4 + j;
                float dot = __fadd_rn(accT[i][j], accP[i][j]);
                float v = __fadd_rn(dot, bias[c]);
                X[(size_t)r * N + c] = fmaxf(v, 0.f);
            }
        }
    }
}

// ---- cls/reg heads: Eigen-panelized fp32 (panels [0,320) and [320,512)) -----
__global__ void __launch_bounds__(256) cls_reg_kernel()
{
    __shared__ __align__(16) float xs[8 * 512];
    int p0 = blockIdx.x * 8;
    int tid = threadIdx.x;
    for (int u = tid; u < 8 * 512; u += 256) {
        int pl = u >> 9;
        int p = p0 + pl;
        xs[u] = (p < NPOS) ? g_x[(size_t)p * CC + (u & 511)] : 0.f;
    }
    __syncthreads();
    for (int t = tid; t < 8 * 45; t += 256) {
        int pl = t / 45, o = t % 45;
        int p = p0 + pl;
        if (p >= NPOS) continue;
        const float* xrow = xs + pl * 512;
        float a0 = 0.f, a1 = 0.f;
#pragma unroll 8
        for (int ci = 0; ci < EIG_KC; ci++)
            a0 = fmaf(xrow[ci], g_wcomb[ci * 45 + o], a0);
#pragma unroll 8
        for (int ci = EIG_KC; ci < 512; ci++)
            a1 = fmaf(xrow[ci], g_wcomb[ci * 45 + o], a1);
        float dot = __fadd_rn(a0, a1);
        float lg = __fadd_rn(dot, g_bcomb[o]);
        if (o < 9) {
            g_obj[p * 9 + o] = xla_logistic_f32(lg);
        } else {
            g_regall[p * 36 + (o - 9)] = lg;
        }
    }
}

// ------------------ exact stable top-K (rank counting, 4x tiled) -------------
// grid (22, 6); each thread counts for 4 candidates i (stride 256).
__global__ void __launch_bounds__(256) topk_count_kernel()
{
    __shared__ float sv[3750];
    int base = blockIdx.y * 3750;
    for (int jj = threadIdx.x; jj < 3750; jj += 256) sv[jj] = g_obj[base + jj];
    __syncthreads();
    int i0 = blockIdx.x * 1024 + threadIdx.x;
    float vi[4]; int cnt[4];
#pragma unroll
    for (int u = 0; u < 4; u++) {
        int i = i0 + u * 256;
        vi[u] = (i < NOBJ) ? g_obj[i] : -1.f;
        cnt[u] = 0;
    }
#pragma unroll 2
    for (int j = 0; j < 3750; j++) {
        float vj = sv[j];
        int gj = base + j;
#pragma unroll
        for (int u = 0; u < 4; u++) {
            int i = i0 + u * 256;
            cnt[u] += (vj > vi[u]) || (vj == vi[u] && gj < i);
        }
    }
#pragma unroll
    for (int u = 0; u < 4; u++) {
        int i = i0 + u * 256;
        if (i < NOBJ && cnt[u] > 0) atomicAdd(&g_cnt[i], cnt[u]);
    }
}

__global__ void topk_place_kernel()
{
    int i = blockIdx.x * 256 + threadIdx.x;
    if (i < NOBJ) {
        int c = g_cnt[i];
        if (c < KKT) g_topk[c] = i;
    }
}

// ---- ROI align (fused box decode) -> pooled bf16 hi/lo + out_boxes ----------
__global__ void __launch_bounds__(256) roi_align_kernel(const float* __restrict__ feat,
                                                        float* __restrict__ out_boxes)
{
    __shared__ float bx[4];
    __shared__ float sfx[3], sfy[3];
    __shared__ int sx0[3], sx1[3], sy0[3], sy1[3];
    int r = blockIdx.x;
    int tid = threadIdx.x;
    if (tid == 0) {
        int i = g_topk[r];
        float s0 = xla_logistic_f32(g_regall[i * 4 + 0]);
        float s1 = xla_logistic_f32(g_regall[i * 4 + 1]);
        float s2 = xla_logistic_f32(g_regall[i * 4 + 2]);
        float s3 = xla_logistic_f32(g_regall[i * 4 + 3]);
        float x1 = __fmul_rn(s0, 48.f);
        float x2 = __fadd_rn(__fadd_rn(x1, 1.f), __fmul_rn(s1, __fadd_rn(49.f, -x1)));
        float y1 = __fmul_rn(s2, 48.f);
        float y2 = __fadd_rn(__fadd_rn(y1, 1.f), __fmul_rn(s3, __fadd_rn(49.f, -y1)));
        bx[0] = x1; bx[1] = x2; bx[2] = y1; bx[3] = y2;
        out_boxes[r * 4 + 0] = x1; out_boxes[r * 4 + 1] = x2;
        out_boxes[r * 4 + 2] = y1; out_boxes[r * 4 + 3] = y2;
    }
    __syncthreads();
    if (tid < 3) {
        float x1 = bx[0], x2 = bx[1], y1 = bx[2], y2 = bx[3];
        float t = ((float)tid + 0.5f) / 3.0f;
        float xsv = x1 + (x2 - x1) * t;
        float ysv = y1 + (y2 - y1) * t;
        float x0f = floorf(xsv), y0f = floorf(ysv);
        sfx[tid] = xsv - x0f;  sfy[tid] = ysv - y0f;
        int x0 = min(max((int)x0f, 0), WWD - 1);
        int y0 = min(max((int)y0f, 0), HH - 1);
        sx0[tid] = x0; sx1[tid] = min(x0 + 1, WWD - 1);
        sy0[tid] = y0; sy1[tid] = min(y0 + 1, HH - 1);
    }
    __syncthreads();
    const float4* f4 = (const float4*)feat;
    for (int id = tid; id < 9 * 128; id += 256) {
        int cell = id >> 7, c4 = id & 127;
        int py = cell / 3, px = cell % 3;
        float fx = sfx[px], fy = sfy[py];
        float w00 = (1.f - fy) * (1.f - fx);
        float w01 = (1.f - fy) * fx;
        float w10 = fy * (1.f - fx);
        float w11 = fy * fx;
        float4 v00 = f4[(size_t)(sy0[py] * WWD + sx0[px]) * 128 + c4];
        float4 v01 = f4[(size_t)(sy0[py] * WWD + sx1[px]) * 128 + c4];
        float4 v10 = f4[(size_t)(sy1[py] * WWD + sx0[px]) * 128 + c4];
        float4 v11 = f4[(size_t)(sy1[py] * WWD + sx1[px]) * 128 + c4];
        float4 o;
        o.x = w00 * v00.x + w01 * v01.x + w10 * v10.x + w11 * v11.x;
        o.y = w00 * v00.y + w01 * v01.y + w10 * v10.y + w11 * v11.y;
        o.z = w00 * v00.z + w01 * v01.z + w10 * v10.z + w11 * v11.z;
        o.w = w00 * v00.w + w01 * v01.w + w10 * v10.w + w11 * v11.w;
        size_t b = (size_t)r * DIN + id * 4;
        float vv[4] = {o.x, o.y, o.z, o.w};
#pragma unroll
        for (int q = 0; q < 4; q++) {
            __nv_bfloat16 hi = __float2bfloat16(vv[q]);
            g_ph[b + q] = hi;
            g_pl[b + q] = __float2bfloat16(vv[q] - __bfloat162float(hi));
        }
    }
}

// ========== bf16 split-2 GEMM on mma.sync (HMMA): C = relu(A@B^T + b) ========
// 512 threads / 16 warps, CTA tile 128x128, warp tile 32x32, BK=32, 3-stage
// cp.async pipeline. B fragments via ldmatrix.x4 (2 n-tiles per instruction).
// 3 passes: AhBh + AhBl + AlBh (split-2 fp32-accurate product).
#define MMLD   40
#define MMARRB (128 * MMLD * 2)       // bytes per array (10240)
#define MMBUFB (4 * MMARRB)           // bytes per stage  (40960)
#define MMSMEM (3 * MMBUFB)           // 122880 (3 stages)
template<int EPI>
__global__ void __launch_bounds__(512, 1) mma_gemm_kernel(
    const __nv_bfloat16* __restrict__ Ah, const __nv_bfloat16* __restrict__ Al,
    const __nv_bfloat16* __restrict__ Bh, const __nv_bfloat16* __restrict__ Bl,
    const float* __restrict__ bias,
    float* __restrict__ Cf, __nv_bfloat16* __restrict__ Ch, __nv_bfloat16* __restrict__ Cl,
    int M, int N, int K)
{
    extern __shared__ __align__(16) char smem_bf[];
    const uint32_t sbase = smem_u32(smem_bf);
    const int tid = threadIdx.x;
    const int wid = tid >> 5, lane = tid & 31;
    const int m0 = blockIdx.y * 128, n0 = blockIdx.x * 128;
    const int wm = wid >> 2, wn = wid & 3;       // 4x4 warp grid, 32x32 each

    const __nv_bfloat16* gsrc[4] = {
        Ah + (size_t)m0 * K, Al + (size_t)m0 * K,
        Bh + (size_t)n0 * K, Bl + (size_t)n0 * K };

    const int grow = tid >> 2;            // 0..127
    const int gcol = (tid & 3) * 8;
    const uint32_t sst = (uint32_t)grow * 80 + (uint32_t)(tid & 3) * 16;

    // ldmatrix lane address components (A: 16x16 x4; B: 16rows x4 -> 2 n-tiles)
    const int aRow = (lane & 7) + ((lane >> 3) & 1) * 8;
    const int aCol = (lane >> 4) * 8;
    const int bqRow = ((lane >> 4) << 3) + (lane & 7);   // 0..15
    const uint32_t bqColB = ((lane >> 3) & 1) * 16;      // byte offset: k half

    float acc[2][4][4];
#pragma unroll
    for (int mt = 0; mt < 2; mt++)
#pragma unroll
        for (int nt = 0; nt < 4; nt++)
#pragma unroll
            for (int r = 0; r < 4; r++) acc[mt][nt][r] = 0.f;

    const int NC = K / 32;
#pragma unroll
    for (int pc = 0; pc < 2; pc++) {
        int k0 = pc * 32;
#pragma unroll
        for (int a = 0; a < 4; a++) {
            uint32_t dst = sbase + (uint32_t)pc * MMBUFB + (uint32_t)a * MMARRB + sst;
            const __nv_bfloat16* src = gsrc[a] + (size_t)grow * K + k0 + gcol;
            CP_ASYNC16(dst, src);
        }
        CP_COMMIT();
    }

    for (int t = 0; t < NC; ++t) {
        CP_WAIT1();
        __syncthreads();
        const int stg = t % 3;
        const uint32_t bb = sbase + (uint32_t)stg * MMBUFB;
#pragma unroll
        for (int kk = 0; kk < 2; kk++) {
            const uint32_t acb = (uint32_t)(kk * 16 + aCol) * 2;
            const uint32_t bkb = (uint32_t)kk * 32 + bqColB;
            uint32_t ah[2][4], al[2][4], bh[8], bl[8];
#pragma unroll
            for (int mt = 0; mt < 2; mt++)
                ldsm_x4(bb + (uint32_t)(wm * 32 + mt * 16 + aRow) * 80 + acb, ah[mt]);
#pragma unroll
            for (int p = 0; p < 2; p++)
                ldsm_x4(bb + 3 * MMARRB + (uint32_t)(wn * 32 + p * 16 + bqRow) * 80 + bkb, &bl[p * 4]);
#pragma unroll
            for (int mt = 0; mt < 2; mt++)
#pragma unroll
                for (int nt = 0; nt < 4; nt++)
                    mma_bf16(acc[mt][nt], ah[mt], &bl[nt * 2]);   // Ah * Bl
#pragma unroll
            for (int p = 0; p < 2; p++)
                ldsm_x4(bb + 2 * MMARRB + (uint32_t)(wn * 32 + p * 16 + bqRow) * 80 + bkb, &bh[p * 4]);
#pragma unroll
            for (int mt = 0; mt < 2; mt++)
#pragma unroll
                for (int nt = 0; nt < 4; nt++)
                    mma_bf16(acc[mt][nt], ah[mt], &bh[nt * 2]);   // Ah * Bh
#pragma unroll
            for (int mt = 0; mt < 2; mt++)
                ldsm_x4(bb + 1 * MMARRB + (uint32_t)(wm * 32 + mt * 16 + aRow) * 80 + acb, al[mt]);
#pragma unroll
            for (int mt = 0; mt < 2; mt++)
#pragma unroll
                for (int nt = 0; nt < 4; nt++)
                    mma_bf16(acc[mt][nt], al[mt], &bh[nt * 2]);   // Al * Bh
        }
        if (t + 2 < NC) {
            int c = t + 2;
            int k0 = c * 32;
            uint32_t db = sbase + (uint32_t)(c % 3) * MMBUFB;
#pragma unroll
            for (int a = 0; a < 4; a++) {
                uint32_t dst = db + (uint32_t)a * MMARRB + sst;
                const __nv_bfloat16* src = gsrc[a] + (size_t)grow * K + k0 + gcol;
                CP_ASYNC16(dst, src);
            }
            CP_COMMIT();
        }
    }

    // epilogue: packed stores
#pragma unroll
    for (int mt = 0; mt < 2; mt++) {
#pragma unroll
        for (int nt = 0; nt < 4; nt++) {
#pragma unroll
            for (int rp = 0; rp < 2; rp++) {
                int row = m0 + wm * 32 + mt * 16 + (lane >> 2) + rp * 8;
                int col = n0 + wn * 32 + nt * 8 + 2 * (lane & 3);
                float v0 = acc[mt][nt][rp * 2 + 0] + __ldg(&bias[col]);
                float v1 = acc[mt][nt][rp * 2 + 1] + __ldg(&bias[col + 1]);
                v0 = fmaxf(v0, 0.f); v1 = fmaxf(v1, 0.f);
                if (EPI == 0) {
                    __nv_bfloat16 h0 = __float2bfloat16(v0);
                    __nv_bfloat16 h1 = __float2bfloat16(v1);
                    __nv_bfloat162 hv; hv.x = h0; hv.y = h1;
                    __nv_bfloat162 lv;
                    lv.x = __float2bfloat16(v0 - __bfloat162float(h0));
                    lv.y = __float2bfloat16(v1 - __bfloat162float(h1));
                    *(__nv_bfloat162*)&Ch[(size_t)row * N + col] = hv;
                    *(__nv_bfloat162*)&Cl[(size_t)row * N + col] = lv;
                } else {
                    float2 fv; fv.x = v0; fv.y = v1;
                    *(float2*)&Cf[(size_t)row * N + col] = fv;
                }
            }
        }
    }
}

// ---------- FC8 (two 4096x20 heads, N=40) + fused class softmax (d) ----------
__global__ void __launch_bounds__(256) fc8_kernel()
{
    __shared__ float hs[32 * 65];
    __shared__ float ws[64 * 40];
    __shared__ float ls[32][41];
    int r0 = blockIdx.x * 32;
    int tid = threadIdx.x;
    int rl = tid >> 3, og = tid & 7;
    float acc[5] = {0.f, 0.f, 0.f, 0.f, 0.f};
    for (int k0 = 0; k0 < F7; k0 += 64) {
        __syncthreads();
        for (int u = tid; u < 32 * 16; u += 256) {
            int rr = u >> 4, k4 = u & 15;
            float4 v = *(const float4*)&g_h7[(size_t)(r0 + rr) * F7 + k0 + k4 * 4];
            hs[rr * 65 + k4 * 4 + 0] = v.x;
            hs[rr * 65 + k4 * 4 + 1] = v.y;
            hs[rr * 65 + k4 * 4 + 2] = v.z;
            hs[rr * 65 + k4 * 4 + 3] = v.w;
        }
        for (int u = tid; u < 64 * 40; u += 256)
            ws[u] = g_w8[(size_t)k0 * 40 + u];
        __syncthreads();
#pragma unroll 4
        for (int k = 0; k < 64; k++) {
            float h = hs[rl * 65 + k];
            const float* wp = &ws[k * 40 + og * 5];
#pragma unroll
            for (int j = 0; j < 5; j++) acc[j] = fmaf(h, wp[j], acc[j]);
        }
    }
#pragma unroll
    for (int j = 0; j < 5; j++) {
        int o = og * 5 + j;
        float lg = acc[j] + g_b8[o];
        g_logits[(size_t)(r0 + rl) * 40 + o] = lg;
        ls[rl][o] = lg;
    }
    __syncthreads();
    // fused per-row softmax over classes (d)
    if (tid < 32) {
        const float* lp = &ls[tid][20];
        float m = -1e30f;
#pragma unroll
        for (int o = 0; o < 20; o++) m = fmaxf(m, lp[o]);
        float e[20]; float s = 0.f;
#pragma unroll
        for (int o = 0; o < 20; o++) { e[o] = expf(lp[o] - m); s += e[o]; }
        float* dp = &g_dsm[(size_t)(r0 + tid) * 20];
#pragma unroll
        for (int o = 0; o < 20; o++) dp[o] = e[o] / s;
    }
}

// --------- softmax over regions (c) + scores + clipped class sums ------------
__global__ void __launch_bounds__(256) final_kernel(float* __restrict__ out,
                                                    float* __restrict__ out_scores)
{
    __shared__ float red[256];
    __shared__ float mS[2];
    int j = blockIdx.x, tid = threadIdx.x;

    float m = -1e30f;
    for (int r = tid; r < KKT; r += 256) m = fmaxf(m, g_logits[(size_t)r * 40 + j]);
    red[tid] = m; __syncthreads();
    for (int s = 128; s > 0; s >>= 1) {
        if (tid < s) red[tid] = fmaxf(red[tid], red[tid + s]);
        __syncthreads();
    }
    if (tid == 0) mS[0] = red[0];
    __syncthreads();
    m = mS[0];

    float s = 0.f;
    for (int r = tid; r < KKT; r += 256) s += expf(g_logits[(size_t)r * 40 + j] - m);
    red[tid] = s; __syncthreads();
    for (int st = 128; st > 0; st >>= 1) {
        if (tid < st) red[tid] += red[tid + st];
        __syncthreads();
    }
    if (tid == 0) mS[1] = red[0];
    __syncthreads();
    float S = mS[1];

    float tot = 0.f;
    for (int r = tid; r < KKT; r += 256) {
        float cv = expf(g_logits[(size_t)r * 40 + j] - m) / S;
        float sc = cv * g_dsm[r * 20 + j];
        out_scores[r * 20 + j] = sc;
        tot += sc;
    }
    red[tid] = tot; __syncthreads();
    for (int st = 128; st > 0; st >>= 1) {
        if (tid < st) red[tid] += red[tid + st];
        __syncthreads();
    }
    if (tid == 0) out[j] = fminf(fmaxf(red[0], 0.f), 1.f);
}

// ------------------------- launcher ------------------------------------------
extern "C" void kernel_launch(void* const* d_in, const int* in_sizes, int n_in,
                              void* d_out, int out_size)
{
    const float* features = (const float*)d_in[0];
    const float* rpn_w  = (const float*)d_in[2];
    const float* rpn_b  = (const float*)d_in[3];
    const float* cls_w  = (const float*)d_in[4];
    const float* cls_b  = (const float*)d_in[5];
    const float* reg_w  = (const float*)d_in[6];
    const float* reg_b  = (const float*)d_in[7];
    const float* fc6_w  = (const float*)d_in[8];
    const float* fc6_b  = (const float*)d_in[9];
    const float* fc7_w  = (const float*)d_in[10];
    const float* fc7_b  = (const float*)d_in[11];
    const float* fc8c_w = (const float*)d_in[12];
    const float* fc8c_b = (const float*)d_in[13];
    const float* fc8d_w = (const float*)d_in[14];
    const float* fc8d_b = (const float*)d_in[15];

    float* out        = (float*)d_out;
    float* out_scores = out + NCLS;
    float* out_boxes  = out + NCLS + KKT * NCLS;

    void *p_acol, *p_x, *p_cnt;
    void *p_ph, *p_pl, *p_w6h, *p_w6l, *p_w7h, *p_w7l, *p_h6h, *p_h6l, *p_h7;
    cudaGetSymbolAddress(&p_acol, g_acol);
    cudaGetSymbolAddress(&p_x,    g_x);
    cudaGetSymbolAddress(&p_cnt,  g_cnt);
    cudaGetSymbolAddress(&p_ph,   g_ph);
    cudaGetSymbolAddress(&p_pl,   g_pl);
    cudaGetSymbolAddress(&p_w6h,  g_w6h);
    cudaGetSymbolAddress(&p_w6l,  g_w6l);
    cudaGetSymbolAddress(&p_w7h,  g_w7h);
    cudaGetSymbolAddress(&p_w7l,  g_w7l);
    cudaGetSymbolAddress(&p_h6h,  g_h6h);
    cudaGetSymbolAddress(&p_h6l,  g_h6l);
    cudaGetSymbolAddress(&p_h7,   g_h7);

    cudaFuncSetAttribute(mma_gemm_kernel<0>, cudaFuncAttributeMaxDynamicSharedMemorySize, MMSMEM);
    cudaFuncSetAttribute(mma_gemm_kernel<1>, cudaFuncAttributeMaxDynamicSharedMemorySize, MMSMEM);

    // 1. pack aux weights
    build_aux_kernel<<<(CC*45 + F7*40 + 85 + 255) / 256, 256>>>(
        cls_w, cls_b, reg_w, reg_b, fc8c_w, fc8c_b, fc8d_w, fc8d_b);

    // 2. weight transpose + bf16 split for FC6/FC7
    wsplit_kernel<<<dim3(F6 / 32, DIN / 32), dim3(32, 8)>>>(
        fc6_w, (__nv_bfloat16*)p_w6h, (__nv_bfloat16*)p_w6l, DIN, F6);
    wsplit_kernel<<<dim3(F7 / 32, F6 / 32), dim3(32, 8)>>>(
        fc7_w, (__nv_bfloat16*)p_w7h, (__nv_bfloat16*)p_w7l, F6, F7);

    // 3. im2col + RPN conv (bit-exact fp32, Eigen kc=320 panels)
    im2col_kernel<<<NPOS * 4, 128>>>(features);
    conv_sgemm_kernel<<<dim3(512 / 64, (NPOS + 63) / 64), 256>>>(
        (const float*)p_acol, rpn_w, rpn_b, (float*)p_x);

    // 4. cls/reg heads
    cls_reg_kernel<<<(NPOS + 7) / 8, 256>>>();

    // 5. exact stable top-K (ties: lower index first)
    cudaMemsetAsync(p_cnt, 0, NOBJ * sizeof(int), 0);
    topk_count_kernel<<<dim3(22, 6), 256>>>();
    topk_place_kernel<<<88, 256>>>();

    // 6. ROI align (fused box decode) -> pooled bf16 hi/lo + out_boxes
    roi_align_kernel<<<KKT, 256>>>(features, out_boxes);

    // 7. FC6 on HMMA: [2048,4608] @ [4608,9216]^T(split) + relu -> bf16 hi/lo
    mma_gemm_kernel<0><<<dim3(F6 / 128, KKT / 128), 512, MMSMEM>>>(
        (const __nv_bfloat16*)p_ph, (const __nv_bfloat16*)p_pl,
        (const __nv_bfloat16*)p_w6h, (const __nv_bfloat16*)p_w6l,
        fc6_b, nullptr, (__nv_bfloat16*)p_h6h, (__nv_bfloat16*)p_h6l,
        KKT, F6, DIN);

    // 8. FC7 on HMMA: [2048,9216] @ [9216,4096]^T(split) + relu -> fp32
    mma_gemm_kernel<1><<<dim3(F7 / 128, KKT / 128), 512, MMSMEM>>>(
        (const __nv_bfloat16*)p_h6h, (const __nv_bfloat16*)p_h6l,
        (const __nv_bfloat16*)p_w7h, (const __nv_bfloat16*)p_w7l,
        fc7_b, (float*)p_h7, nullptr, nullptr,
        KKT, F7, F6);

    // 9-10. FC8 + fused d-softmax, then region softmax + scores
    fc8_kernel<<<KKT / 32, 256>>>();
    final_kernel<<<NCLS, 256>>>(out, out_scores);

    (void)in_sizes; (void)n_in; (void)out_size;
}